// round 1
// baseline (speedup 1.0000x reference)
#include <cuda_runtime.h>
#include <math.h>

#define B_SZ    16
#define L_SEQ   4096
#define DM      256
#define NST     32          // D_STATE/2 complex modes
#define H2      512         // 2*D_MODEL
#define OUTC    512
#define KDIM    512

// ---------------- scratch (no allocs allowed) ----------------
__device__ float4 g_wc[2][DM][NST];                       // w.re, w.im, 2c.re, 2c.im
__device__ float  g_act[(size_t)B_SZ * H2 * L_SEQ];       // gelu(conv out), [b][c][l], 128 MiB

// ---------------- K1: per-mode constants ----------------
__global__ void k_const(const float* __restrict__ ldt_fw, const float* __restrict__ lAr_fw,
                        const float* __restrict__ Ai_fw,  const float* __restrict__ C_fw,
                        const float* __restrict__ ldt_bw, const float* __restrict__ lAr_bw,
                        const float* __restrict__ Ai_bw,  const float* __restrict__ C_bw)
{
    int idx = blockIdx.x * blockDim.x + threadIdx.x;      // 0..16383
    int n   = idx & 31;
    int d   = (idx >> 5) & 255;
    int dir = idx >> 13;

    const float* ldt = dir ? ldt_bw : ldt_fw;
    const float* lAr = dir ? lAr_bw : lAr_fw;
    const float* Ai  = dir ? Ai_bw  : Ai_fw;
    const float* C   = dir ? C_bw   : C_fw;

    float dt = expf(ldt[d]);
    float Ar = -expf(lAr[d * 32 + n]);
    float Aim = Ai[d * 32 + n];

    float xr = Ar * dt, xi = Aim * dt;
    float e  = expf(xr);
    float wr = e * cosf(xi);
    float wi = e * sinf(xi);

    // (exp(dtA) - 1) / (A + 1e-8)
    float nr = wr - 1.0f, ni = wi;
    float dr = Ar + 1e-8f, di = Aim;
    float den = dr * dr + di * di;
    float rr = (nr * dr + ni * di) / den;
    float ri = (ni * dr - nr * di) / den;

    float Cr  = C[(d * 32 + n) * 2 + 0];
    float Cim = C[(d * 32 + n) * 2 + 1];
    float cr = Cr * rr - Cim * ri;
    float ci = Cr * ri + Cim * rr;

    g_wc[dir][d][n] = make_float4(wr, wi, 2.0f * cr, 2.0f * ci);
}

// ---------------- K2: bidirectional SSM scan + Dskip + GELU ----------------
#define TILE_T 64
#define CHB    64

__global__ void __launch_bounds__(256, 1)
k_scan(const float* __restrict__ x, const float* __restrict__ Dskip)
{
    // grid.x = 16 * 2 * 4 = 128
    int b   = blockIdx.x >> 3;
    int dir = (blockIdx.x >> 2) & 1;
    int d0  = (blockIdx.x & 3) * CHB;

    int tid = threadIdx.x;
    int ch  = tid >> 2;           // 0..63 channel within block
    int sub = tid & 3;            // 0..3: which 8 states
    int d   = d0 + ch;

    __shared__ float su[TILE_T][CHB];
    __shared__ float sg[TILE_T][CHB + 1];

    float wr[8], wi[8], cr[8], ci[8];
    {
        const float4* wc = &g_wc[dir][d][sub * 8];
#pragma unroll
        for (int i = 0; i < 8; i++) {
            float4 v = wc[i];
            wr[i] = v.x; wi[i] = v.y; cr[i] = v.z; ci[i] = v.w;
        }
    }
    float sre[8], sim[8];
#pragma unroll
    for (int i = 0; i < 8; i++) { sre[i] = 0.f; sim[i] = 0.f; }

    float Dv = Dskip[d];

    const float* xb = x + (size_t)b * L_SEQ * DM + d0;
    float* gout = g_act + ((size_t)b * H2 + (size_t)dir * DM + d0) * L_SEQ;

    for (int t0 = 0; t0 < L_SEQ; t0 += TILE_T) {
        // load input tile (coalesced over channels)
        for (int i = tid; i < TILE_T * CHB; i += 256) {
            int ll = i >> 6;
            int cc = i & 63;
            int step = t0 + ll;
            int lg = dir ? (L_SEQ - 1 - step) : step;
            su[ll][cc] = xb[(size_t)lg * DM + cc];
        }
        __syncthreads();

#pragma unroll 2
        for (int ll = 0; ll < TILE_T; ll++) {
            float u = su[ll][ch];
            float acc = 0.f;
#pragma unroll
            for (int i = 0; i < 8; i++) {
                float sr_old = sre[i];
                float t = fmaf(wr[i], sr_old, u);
                sre[i] = fmaf(-wi[i], sim[i], t);
                sim[i] = fmaf(wi[i], sr_old, wr[i] * sim[i]);
                acc = fmaf(cr[i], sre[i], acc);
                acc = fmaf(-ci[i], sim[i], acc);
            }
            acc += __shfl_xor_sync(0xffffffffu, acc, 1);
            acc += __shfl_xor_sync(0xffffffffu, acc, 2);
            if (sub == 0) {
                float y = fmaf(Dv, u, acc);
                float gy = 0.5f * y * (1.0f + erff(y * 0.70710678118654752f));
                sg[ll][ch] = gy;
            }
        }
        __syncthreads();

        // write gelu'd outputs (coalesced over l within channel rows)
        for (int i = tid; i < TILE_T * CHB; i += 256) {
            int cc = i >> 6;
            int ll = i & 63;
            int step = t0 + ll;
            int lg = dir ? (L_SEQ - 1 - step) : step;
            gout[(size_t)cc * L_SEQ + lg] = sg[ll][cc];
        }
        __syncthreads();
    }
}

// ---------------- K3: fp32 GEMM (1024x512 @ 512xN) + bias + GLU ----------------
#define BM 64     // c outputs per block (each has an 'a' and 'b' row)
#define BN 128    // positions per block
#define BK 16

__global__ void __launch_bounds__(256, 2)
k_gemm(const float* __restrict__ W, const float* __restrict__ bias,
       float* __restrict__ out)
{
    int pb = blockIdx.x;                 // 0..511
    int mb = blockIdx.y;                 // 0..7
    int b  = pb >> 5;                    // 32 pos-blocks per batch
    int l0 = (pb & 31) * BN;
    int c0 = mb * BM;

    __shared__ float sWa[BK][BM + 4];
    __shared__ float sWb[BK][BM + 4];
    __shared__ float sG[BK][BN];

    int tid = threadIdx.x;
    int ty = tid >> 4;                   // 0..15: c group
    int tx = tid & 15;                   // 0..15: pos group

    float accA[4][8], accB[4][8];
#pragma unroll
    for (int i = 0; i < 4; i++)
#pragma unroll
        for (int j = 0; j < 8; j++) { accA[i][j] = 0.f; accB[i][j] = 0.f; }

    const float* gbase = g_act + (size_t)b * H2 * L_SEQ + l0;

    for (int k0 = 0; k0 < KDIM; k0 += BK) {
        {   // W tiles (transposed into shared)
            int r  = tid >> 2;           // 0..63
            int kq = tid & 3;            // 0..3
            float4 va = *(const float4*)(W + (size_t)(c0 + r) * KDIM + k0 + kq * 4);
            sWa[kq * 4 + 0][r] = va.x; sWa[kq * 4 + 1][r] = va.y;
            sWa[kq * 4 + 2][r] = va.z; sWa[kq * 4 + 3][r] = va.w;
            float4 vb = *(const float4*)(W + (size_t)(c0 + 512 + r) * KDIM + k0 + kq * 4);
            sWb[kq * 4 + 0][r] = vb.x; sWb[kq * 4 + 1][r] = vb.y;
            sWb[kq * 4 + 2][r] = vb.z; sWb[kq * 4 + 3][r] = vb.w;
        }
        {   // G tile: rows are l-contiguous
            int r  = tid >> 4;           // 0..15 (k row)
            int cq = tid & 15;
            *(float4*)&sG[r][cq * 4]      = *(const float4*)(gbase + (size_t)(k0 + r) * L_SEQ + cq * 4);
            *(float4*)&sG[r][cq * 4 + 64] = *(const float4*)(gbase + (size_t)(k0 + r) * L_SEQ + cq * 4 + 64);
        }
        __syncthreads();

#pragma unroll
        for (int k = 0; k < BK; k++) {
            float4 a4 = *(const float4*)&sWa[k][ty * 4];
            float4 b4 = *(const float4*)&sWb[k][ty * 4];
            float4 g0 = *(const float4*)&sG[k][tx * 8];
            float4 g1 = *(const float4*)&sG[k][tx * 8 + 4];
            float av[4] = {a4.x, a4.y, a4.z, a4.w};
            float bv[4] = {b4.x, b4.y, b4.z, b4.w};
            float gv[8] = {g0.x, g0.y, g0.z, g0.w, g1.x, g1.y, g1.z, g1.w};
#pragma unroll
            for (int i = 0; i < 4; i++)
#pragma unroll
                for (int j = 0; j < 8; j++) {
                    accA[i][j] = fmaf(av[i], gv[j], accA[i][j]);
                    accB[i][j] = fmaf(bv[i], gv[j], accB[i][j]);
                }
        }
        __syncthreads();
    }

    // epilogue: bias + GLU, write [b, l, c]
    float ba[4], bb[4];
#pragma unroll
    for (int i = 0; i < 4; i++) {
        ba[i] = bias[c0 + ty * 4 + i];
        bb[i] = bias[512 + c0 + ty * 4 + i];
    }
#pragma unroll
    for (int j = 0; j < 8; j++) {
        int l = l0 + tx * 8 + j;
        float4 o;
        float r[4];
#pragma unroll
        for (int i = 0; i < 4; i++) {
            float av = accA[i][j] + ba[i];
            float bvv = accB[i][j] + bb[i];
            r[i] = av / (1.0f + expf(-bvv));
        }
        o.x = r[0]; o.y = r[1]; o.z = r[2]; o.w = r[3];
        *(float4*)(out + ((size_t)b * L_SEQ + l) * OUTC + c0 + ty * 4) = o;
    }
}

// ---------------- K4: LayerNorm over last dim (in-place on out) ----------------
__global__ void __launch_bounds__(128)
k_ln(float* __restrict__ out, const float* __restrict__ gamma, const float* __restrict__ beta)
{
    int tid = threadIdx.x;                        // 0..127, 4 floats each
    float* row = out + (size_t)blockIdx.x * OUTC;
    float4 v = reinterpret_cast<float4*>(row)[tid];

    __shared__ float red[8];

    float s = v.x + v.y + v.z + v.w;
#pragma unroll
    for (int o = 16; o; o >>= 1) s += __shfl_xor_sync(0xffffffffu, s, o);
    if ((tid & 31) == 0) red[tid >> 5] = s;
    __syncthreads();
    float mu = (red[0] + red[1] + red[2] + red[3]) * (1.0f / OUTC);

    float dx = v.x - mu, dy = v.y - mu, dz = v.z - mu, dw = v.w - mu;
    float sq = dx * dx + dy * dy + dz * dz + dw * dw;
#pragma unroll
    for (int o = 16; o; o >>= 1) sq += __shfl_xor_sync(0xffffffffu, sq, o);
    if ((tid & 31) == 0) red[4 + (tid >> 5)] = sq;
    __syncthreads();
    float var = (red[4] + red[5] + red[6] + red[7]) * (1.0f / OUTC);
    float inv = rsqrtf(var + 1e-5f);

    float4 g4 = reinterpret_cast<const float4*>(gamma)[tid];
    float4 b4 = reinterpret_cast<const float4*>(beta)[tid];
    float4 o;
    o.x = dx * inv * g4.x + b4.x;
    o.y = dy * inv * g4.y + b4.y;
    o.z = dz * inv * g4.z + b4.z;
    o.w = dw * inv * g4.w + b4.w;
    reinterpret_cast<float4*>(row)[tid] = o;
}

// ---------------- launch ----------------
extern "C" void kernel_launch(void* const* d_in, const int* in_sizes, int n_in,
                              void* d_out, int out_size)
{
    const float* x       = (const float*)d_in[0];
    const float* ldt_fw  = (const float*)d_in[1];
    const float* lAr_fw  = (const float*)d_in[2];
    const float* Ai_fw   = (const float*)d_in[3];
    const float* C_fw    = (const float*)d_in[4];
    const float* ldt_bw  = (const float*)d_in[5];
    const float* lAr_bw  = (const float*)d_in[6];
    const float* Ai_bw   = (const float*)d_in[7];
    const float* C_bw    = (const float*)d_in[8];
    const float* Dskip   = (const float*)d_in[9];
    const float* conv_w  = (const float*)d_in[10];
    const float* conv_b  = (const float*)d_in[11];
    const float* ln_g    = (const float*)d_in[12];
    const float* ln_b    = (const float*)d_in[13];
    float* out = (float*)d_out;

    k_const<<<64, 256>>>(ldt_fw, lAr_fw, Ai_fw, C_fw, ldt_bw, lAr_bw, Ai_bw, C_bw);
    k_scan<<<128, 256>>>(x, Dskip);
    dim3 g3(512, 8);
    k_gemm<<<g3, 256>>>(conv_w, conv_b, out);
    k_ln<<<B_SZ * L_SEQ, 128>>>(out, ln_g, ln_b);
}